// round 5
// baseline (speedup 1.0000x reference)
#include <cuda_runtime.h>

#define B_  2
#define C_  512
#define NH  8
#define D_  64
#define S_  2304          // 48*48
#define SCALE 0.125f      // 1/sqrt(64)

// ---------------------------------------------------------------------------
// tf32 helpers
// ---------------------------------------------------------------------------
__device__ __forceinline__ float tf32r(float f) {
    unsigned r;
    asm("cvt.rna.tf32.f32 %0, %1;" : "=r"(r) : "f"(f));
    return __uint_as_float(r);
}
__device__ __forceinline__ void mma_tf32(float c[4],
                                         float a0, float a1, float a2, float a3,
                                         float b0, float b1) {
    asm volatile(
        "mma.sync.aligned.m16n8k8.row.col.f32.tf32.tf32.f32 "
        "{%0,%1,%2,%3}, {%4,%5,%6,%7}, {%8,%9}, {%0,%1,%2,%3};\n"
        : "+f"(c[0]), "+f"(c[1]), "+f"(c[2]), "+f"(c[3])
        : "r"(__float_as_uint(a0)), "r"(__float_as_uint(a1)),
          "r"(__float_as_uint(a2)), "r"(__float_as_uint(a3)),
          "r"(__float_as_uint(b0)), "r"(__float_as_uint(b1)));
}

// Scratch ------------------------------------------------------------------
__device__ float g_q[B_ * NH * D_ * S_];    // [b][n][d][s]
__device__ float g_k[B_ * NH * D_ * S_];    // [b][n][d][s]
__device__ float g_v[B_ * NH * S_ * D_];    // [b][n][s][d]
__device__ float g_attn[B_ * S_ * NH * D_]; // [b][s][n*64+d]

// ---------------------------------------------------------------------------
// QKV projection via tf32 mma.  m = d(64), n = s(64), k = C(512) chunk 32.
// A = W[d][c] (row-major, direct), B = x[c][s] (col-major frag, direct).
// grid (36 s-tiles, 16 bn, 3 proj), block 128 (4 warps, 2x2 of 32x32 tiles).
// ---------------------------------------------------------------------------
__global__ __launch_bounds__(128) void proj_kernel(
    const float* __restrict__ x,
    const float* __restrict__ Wq, const float* __restrict__ bq,
    const float* __restrict__ Wk, const float* __restrict__ bk,
    const float* __restrict__ Wv, const float* __restrict__ bv)
{
    __shared__ float As[64][36];   // [d][c']  A-frag stride 36 (==4 mod 32)
    __shared__ float Bs[32][72];   // [c'][s]  B-frag stride 72 (==8 mod 32)

    const int p  = blockIdx.z;
    const int bn = blockIdx.y;
    const int b  = bn >> 3, n = bn & 7;
    const int s0 = blockIdx.x * 64;

    const float* W    = (p == 0) ? Wq : (p == 1) ? Wk : Wv;
    const float* bias = (p == 0) ? bq : (p == 1) ? bk : bv;

    const int tid  = threadIdx.x;
    const int wid  = tid >> 5, lane = tid & 31;
    const int gid  = lane >> 2, tig = lane & 3;
    const int wm   = wid >> 1, wn = wid & 1;     // warp 32x32 tile coords

    const float* xb = x + (size_t)b * C_ * S_ + s0;
    const float* Wn = W + n * D_ * C_;

    float Cacc[2][4][4] = {};   // [m-atom][n-atom][reg]

    for (int k0 = 0; k0 < C_; k0 += 32) {
        // W tile: 64 rows x 32 cols = 512 float4
        #pragma unroll
        for (int r = 0; r < 4; r++) {
            int i4 = tid + r * 128;
            int dd = i4 >> 3, c4 = (i4 & 7) * 4;
            float4 v = *(const float4*)&Wn[dd * C_ + k0 + c4];
            As[dd][c4]     = tf32r(v.x); As[dd][c4 + 1] = tf32r(v.y);
            As[dd][c4 + 2] = tf32r(v.z); As[dd][c4 + 3] = tf32r(v.w);
        }
        // X tile: 32 rows x 64 cols = 512 float4
        #pragma unroll
        for (int r = 0; r < 4; r++) {
            int i4 = tid + r * 128;
            int cc = i4 >> 4, s4 = (i4 & 15) * 4;
            float4 v = *(const float4*)&xb[(size_t)(k0 + cc) * S_ + s4];
            Bs[cc][s4]     = tf32r(v.x); Bs[cc][s4 + 1] = tf32r(v.y);
            Bs[cc][s4 + 2] = tf32r(v.z); Bs[cc][s4 + 3] = tf32r(v.w);
        }
        __syncthreads();

        #pragma unroll
        for (int kk = 0; kk < 32; kk += 8) {
            float a[2][4];
            #pragma unroll
            for (int i = 0; i < 2; i++) {
                int row = wm * 32 + i * 16;
                a[i][0] = As[row + gid][kk + tig];
                a[i][1] = As[row + gid + 8][kk + tig];
                a[i][2] = As[row + gid][kk + tig + 4];
                a[i][3] = As[row + gid + 8][kk + tig + 4];
            }
            #pragma unroll
            for (int j = 0; j < 4; j++) {
                int col = wn * 32 + j * 8 + gid;
                float b0 = Bs[kk + tig][col];
                float b1 = Bs[kk + tig + 4][col];
                #pragma unroll
                for (int i = 0; i < 2; i++)
                    mma_tf32(Cacc[i][j], a[i][0], a[i][1], a[i][2], a[i][3], b0, b1);
            }
        }
        __syncthreads();
    }

    // Epilogue: rows = d = wm*32 + i*16 + gid(+8);  cols = s = wn*32 + j*8 + 2tig(+1)
    if (p < 2) {
        float* g = ((p == 0) ? g_q : g_k) + (size_t)(b * NH + n) * D_ * S_;
        #pragma unroll
        for (int i = 0; i < 2; i++) {
            int r0 = wm * 32 + i * 16 + gid;
            float bi0 = bias[n * D_ + r0], bi1 = bias[n * D_ + r0 + 8];
            #pragma unroll
            for (int j = 0; j < 4; j++) {
                int col = s0 + wn * 32 + j * 8 + 2 * tig;
                *(float2*)&g[(size_t)r0 * S_ + col] =
                    make_float2(Cacc[i][j][0] + bi0, Cacc[i][j][1] + bi0);
                *(float2*)&g[(size_t)(r0 + 8) * S_ + col] =
                    make_float2(Cacc[i][j][2] + bi1, Cacc[i][j][3] + bi1);
            }
        }
    } else {
        float* g = g_v + (size_t)(b * NH + n) * S_ * D_;   // [s][d]
        #pragma unroll
        for (int i = 0; i < 2; i++) {
            int r0 = wm * 32 + i * 16 + gid;
            float bi0 = bias[n * D_ + r0], bi1 = bias[n * D_ + r0 + 8];
            #pragma unroll
            for (int j = 0; j < 4; j++) {
                int col = s0 + wn * 32 + j * 8 + 2 * tig;
                g[(size_t)col * D_ + r0]           = Cacc[i][j][0] + bi0;
                g[(size_t)(col + 1) * D_ + r0]     = Cacc[i][j][1] + bi0;
                g[(size_t)col * D_ + r0 + 8]       = Cacc[i][j][2] + bi1;
                g[(size_t)(col + 1) * D_ + r0 + 8] = Cacc[i][j][3] + bi1;
            }
        }
    }
}

// ---------------------------------------------------------------------------
// Flash attention with tf32 mma.  q-tile 64, kv-tile 64, d = 64.
// Warp w owns q rows [w*16, w*16+16).  QK: A=Qs[q][d], B=KPs[d][k].
// PV: A=P (KPs reused, [q][k]), B=Vs[k][dv].
// Dynamic smem: Qs[64][72] + KPs[64][72] + Vs[64][72] = 55296 B.
// ---------------------------------------------------------------------------
extern __shared__ float s_attn[];

__global__ __launch_bounds__(128) void attn_kernel()
{
    float (*Qs)[72]  = (float (*)[72])(s_attn);
    float (*KPs)[72] = (float (*)[72])(s_attn + 64 * 72);
    float (*Vs)[72]  = (float (*)[72])(s_attn + 2 * 64 * 72);

    const int bn = blockIdx.y;
    const int b = bn >> 3, n = bn & 7;
    const int q0 = blockIdx.x * 64;
    const int tid = threadIdx.x;
    const int wid = tid >> 5, lane = tid & 31;
    const int gid = lane >> 2, tig = lane & 3;
    const int qr  = wid * 16;

    const float* Q = g_q + (size_t)(b * NH + n) * D_ * S_;  // [d][s]
    const float* K = g_k + (size_t)(b * NH + n) * D_ * S_;  // [d][s]
    const float* V = g_v + (size_t)(b * NH + n) * S_ * D_;  // [s][d]

    // Q transpose into Qs[q][d], scaled + tf32 (once per CTA)
    #pragma unroll
    for (int r = 0; r < 32; r++) {
        int idx = tid + r * 128;
        int dd = idx >> 6, qq = idx & 63;
        Qs[qq][dd] = tf32r(Q[(size_t)dd * S_ + q0 + qq] * SCALE);
    }

    float m0 = -1e30f, m1 = -1e30f, l0 = 0.f, l1 = 0.f;
    float O[8][4] = {};

    for (int k0 = 0; k0 < S_; k0 += 64) {
        // K tile [d][k], V tile [k][d]: 1024 float4 each
        #pragma unroll
        for (int r = 0; r < 8; r++) {
            int i4 = tid + r * 128;
            int row = i4 >> 4, c4 = (i4 & 15) * 4;
            float4 kv = *(const float4*)&K[(size_t)row * S_ + k0 + c4];
            KPs[row][c4]     = tf32r(kv.x); KPs[row][c4 + 1] = tf32r(kv.y);
            KPs[row][c4 + 2] = tf32r(kv.z); KPs[row][c4 + 3] = tf32r(kv.w);
            float4 vv = *(const float4*)&V[(size_t)(k0 + row) * D_ + c4];
            Vs[row][c4]     = tf32r(vv.x); Vs[row][c4 + 1] = tf32r(vv.y);
            Vs[row][c4 + 2] = tf32r(vv.z); Vs[row][c4 + 3] = tf32r(vv.w);
        }
        __syncthreads();

        // S = Q K^T   (warp: 16 x 64)
        float Sc[8][4] = {};
        #pragma unroll
        for (int kk = 0; kk < 64; kk += 8) {
            float a0 = Qs[qr + gid][kk + tig];
            float a1 = Qs[qr + gid + 8][kk + tig];
            float a2 = Qs[qr + gid][kk + tig + 4];
            float a3 = Qs[qr + gid + 8][kk + tig + 4];
            #pragma unroll
            for (int j = 0; j < 8; j++) {
                float b0 = KPs[kk + tig][j * 8 + gid];
                float b1 = KPs[kk + tig + 4][j * 8 + gid];
                mma_tf32(Sc[j], a0, a1, a2, a3, b0, b1);
            }
        }

        // online softmax: thread rows qr+gid (regs 0,1), qr+gid+8 (regs 2,3)
        float r0 = -1e30f, r1 = -1e30f;
        #pragma unroll
        for (int j = 0; j < 8; j++) {
            r0 = fmaxf(r0, fmaxf(Sc[j][0], Sc[j][1]));
            r1 = fmaxf(r1, fmaxf(Sc[j][2], Sc[j][3]));
        }
        r0 = fmaxf(r0, __shfl_xor_sync(0xffffffffu, r0, 1));
        r0 = fmaxf(r0, __shfl_xor_sync(0xffffffffu, r0, 2));
        r1 = fmaxf(r1, __shfl_xor_sync(0xffffffffu, r1, 1));
        r1 = fmaxf(r1, __shfl_xor_sync(0xffffffffu, r1, 2));

        float mn0 = fmaxf(m0, r0), mn1 = fmaxf(m1, r1);
        float corr0 = __expf(m0 - mn0), corr1 = __expf(m1 - mn1);
        float sum0 = 0.f, sum1 = 0.f;
        #pragma unroll
        for (int j = 0; j < 8; j++) {
            Sc[j][0] = __expf(Sc[j][0] - mn0);
            Sc[j][1] = __expf(Sc[j][1] - mn0);
            Sc[j][2] = __expf(Sc[j][2] - mn1);
            Sc[j][3] = __expf(Sc[j][3] - mn1);
            sum0 += Sc[j][0] + Sc[j][1];
            sum1 += Sc[j][2] + Sc[j][3];
        }
        sum0 += __shfl_xor_sync(0xffffffffu, sum0, 1);
        sum0 += __shfl_xor_sync(0xffffffffu, sum0, 2);
        sum1 += __shfl_xor_sync(0xffffffffu, sum1, 1);
        sum1 += __shfl_xor_sync(0xffffffffu, sum1, 2);
        l0 = l0 * corr0 + sum0;  m0 = mn0;
        l1 = l1 * corr1 + sum1;  m1 = mn1;
        #pragma unroll
        for (int j = 0; j < 8; j++) {
            O[j][0] *= corr0; O[j][1] *= corr0;
            O[j][2] *= corr1; O[j][3] *= corr1;
        }

        __syncthreads();   // all warps finished reading K from KPs
        // P -> KPs as A-layout [q][k] (tf32)
        #pragma unroll
        for (int j = 0; j < 8; j++) {
            int col = j * 8 + 2 * tig;
            *(float2*)&KPs[qr + gid][col] =
                make_float2(tf32r(Sc[j][0]), tf32r(Sc[j][1]));
            *(float2*)&KPs[qr + gid + 8][col] =
                make_float2(tf32r(Sc[j][2]), tf32r(Sc[j][3]));
        }
        __syncthreads();

        // O += P @ V
        #pragma unroll
        for (int kk = 0; kk < 64; kk += 8) {
            float a0 = KPs[qr + gid][kk + tig];
            float a1 = KPs[qr + gid + 8][kk + tig];
            float a2 = KPs[qr + gid][kk + tig + 4];
            float a3 = KPs[qr + gid + 8][kk + tig + 4];
            #pragma unroll
            for (int j = 0; j < 8; j++) {
                float b0 = Vs[kk + tig][j * 8 + gid];
                float b1 = Vs[kk + tig + 4][j * 8 + gid];
                mma_tf32(O[j], a0, a1, a2, a3, b0, b1);
            }
        }
        __syncthreads();
    }

    // epilogue
    float inv0 = 1.f / l0, inv1 = 1.f / l1;
    float* A = g_attn + ((size_t)b * S_ + q0) * (NH * D_) + n * D_;
    #pragma unroll
    for (int j = 0; j < 8; j++) {
        int col = j * 8 + 2 * tig;
        *(float2*)&A[(size_t)(qr + gid) * (NH * D_) + col] =
            make_float2(O[j][0] * inv0, O[j][1] * inv0);
        *(float2*)&A[(size_t)(qr + gid + 8) * (NH * D_) + col] =
            make_float2(O[j][2] * inv1, O[j][3] * inv1);
    }
}

// ---------------------------------------------------------------------------
// Output projection via tf32 mma.  m = c(64), n = s(64), k = 512 chunk 32.
// A = Wo[c][j] direct;  B = attn[s][j] -> transposed smem store Bs[j][s].
// ---------------------------------------------------------------------------
__global__ __launch_bounds__(128) void oproj_kernel(
    const float* __restrict__ Wo, const float* __restrict__ bo,
    float* __restrict__ out)
{
    __shared__ float As[64][36];   // [c][j']
    __shared__ float Bs[32][72];   // [j'][s]

    const int b  = blockIdx.z;
    const int c0 = blockIdx.y * 64;
    const int s0 = blockIdx.x * 64;

    const int tid = threadIdx.x;
    const int wid = tid >> 5, lane = tid & 31;
    const int gid = lane >> 2, tig = lane & 3;
    const int wm  = wid >> 1, wn = wid & 1;

    const float* A = g_attn + ((size_t)b * S_ + s0) * C_;

    float Cacc[2][4][4] = {};

    for (int j0 = 0; j0 < C_; j0 += 32) {
        #pragma unroll
        for (int r = 0; r < 4; r++) {
            int i4 = tid + r * 128;
            int cc = i4 >> 3, j4 = (i4 & 7) * 4;
            float4 v = *(const float4*)&Wo[(size_t)(c0 + cc) * C_ + j0 + j4];
            As[cc][j4]     = tf32r(v.x); As[cc][j4 + 1] = tf32r(v.y);
            As[cc][j4 + 2] = tf32r(v.z); As[cc][j4 + 3] = tf32r(v.w);
        }
        #pragma unroll
        for (int r = 0; r < 16; r++) {          // attn tile transposed
            int idx = tid + r * 128;
            int ss = idx >> 5, jj = idx & 31;
            Bs[jj][ss] = tf32r(A[(size_t)ss * C_ + j0 + jj]);
        }
        __syncthreads();

        #pragma unroll
        for (int kk = 0; kk < 32; kk += 8) {
            float a[2][4];
            #pragma unroll
            for (int i = 0; i < 2; i++) {
                int row = wm * 32 + i * 16;
                a[i][0] = As[row + gid][kk + tig];
                a[i][1] = As[row + gid + 8][kk + tig];
                a[i][2] = As[row + gid][kk + tig + 4];
                a[i][3] = As[row + gid + 8][kk + tig + 4];
            }
            #pragma unroll
            for (int j = 0; j < 4; j++) {
                int col = wn * 32 + j * 8 + gid;
                float b0 = Bs[kk + tig][col];
                float b1 = Bs[kk + tig + 4][col];
                #pragma unroll
                for (int i = 0; i < 2; i++)
                    mma_tf32(Cacc[i][j], a[i][0], a[i][1], a[i][2], a[i][3], b0, b1);
            }
        }
        __syncthreads();
    }

    float* ob = out + ((size_t)b * C_ + c0) * S_ + s0;
    #pragma unroll
    for (int i = 0; i < 2; i++) {
        int r0 = wm * 32 + i * 16 + gid;
        float bi0 = bo[c0 + r0], bi1 = bo[c0 + r0 + 8];
        #pragma unroll
        for (int j = 0; j < 4; j++) {
            int col = wn * 32 + j * 8 + 2 * tig;
            *(float2*)&ob[(size_t)r0 * S_ + col] =
                make_float2(Cacc[i][j][0] + bi0, Cacc[i][j][1] + bi0);
            *(float2*)&ob[(size_t)(r0 + 8) * S_ + col] =
                make_float2(Cacc[i][j][2] + bi1, Cacc[i][j][3] + bi1);
        }
    }
}

// ---------------------------------------------------------------------------
extern "C" void kernel_launch(void* const* d_in, const int* in_sizes, int n_in,
                              void* d_out, int out_size)
{
    const float* x  = (const float*)d_in[0];
    const float* Wq = (const float*)d_in[1];
    const float* bq = (const float*)d_in[2];
    const float* Wk = (const float*)d_in[3];
    const float* bk = (const float*)d_in[4];
    const float* Wv = (const float*)d_in[5];
    const float* bv = (const float*)d_in[6];
    const float* Wo = (const float*)d_in[7];
    const float* bo = (const float*)d_in[8];
    float* out = (float*)d_out;

    const int attn_smem = 3 * 64 * 72 * sizeof(float);   // 55296
    cudaFuncSetAttribute(attn_kernel,
                         cudaFuncAttributeMaxDynamicSharedMemorySize, attn_smem);

    proj_kernel <<<dim3(S_ / 64, B_ * NH, 3), 128>>>(x, Wq, bq, Wk, bk, Wv, bv);
    attn_kernel <<<dim3(S_ / 64, B_ * NH), 128, attn_smem>>>();
    oproj_kernel<<<dim3(S_ / 64, C_ / 64, B_), 128>>>(Wo, bo, out);
}